// round 9
// baseline (speedup 1.0000x reference)
#include <cuda_runtime.h>

#define B_TOTAL 131072
#define NFEAT   64
#define NNUM    48
#define NCAT    16
#define NCLS    32
#define H0      40
#define H1      20
#define TBL     1024
#define NCELL   4096
#define KCLAMP  1.0e4f
#define XSYNTH  -16.0f

// device-global scratch (allocation-free)
__device__ float          g_x[NNUM][TBL];     // knot x, padded +huge
__device__ float2         g_ys[NNUM][TBL];    // (y, slope-to-next)
__device__ unsigned short g_bk[NNUM][NCELL];  // bucket -> knot index
__device__ float          g_xT[NNUM * B_TOTAL];  // col-major x, overwritten with y in-place

// ---------------------------------------------------------------------------
// Setup: exact PWL table per numeric feature.
// Net is exactly PWL in scalar x: knots = layer0 zeros U h1 zero-crossings.
// ---------------------------------------------------------------------------
__global__ __launch_bounds__(1024)
void gam_setup_kernel(const float* __restrict__ W0, const float* __restrict__ b0,
                      const float* __restrict__ W1, const float* __restrict__ b1,
                      const float* __restrict__ W2, const float* __restrict__ b2)
{
    const int f   = blockIdx.x;
    const int tid = threadIdx.x;

    __shared__ float sa[H0], sc[H0], sk[H0];
    __shared__ float sH[H0 + 2][H1];
    __shared__ float list[TBL];
    __shared__ float sx[TBL];
    __shared__ float sW1[H0 * H1], sb1[H1], sW2[H1];
    __shared__ float syr, sb2v;
    __shared__ int   cnt;

    if (tid == 0) cnt = 0;
    if (tid < H0) { sa[tid] = W0[f * H0 + tid]; sc[tid] = b0[f * H0 + tid]; }
    for (int i = tid; i < H0 * H1; i += 1024) sW1[i] = W1[f * H0 * H1 + i];
    if (tid < H1) { sb1[tid] = b1[f * H1 + tid]; sW2[tid] = W2[f * H1 + tid]; }
    if (tid == 0) sb2v = b2[f];
    __syncthreads();

    // layer0 knots (clamped), stable rank-sort into sk
    if (tid < H0) {
        float a = sa[tid], c = sc[tid];
        float kx = (a != 0.0f) ? fminf(fmaxf(-c / a, -KCLAMP), KCLAMP) : KCLAMP;
        int r = 0;
        for (int j = 0; j < H0; j++) {
            float aj = sa[j], cj = sc[j];
            float kj = (aj != 0.0f) ? fminf(fmaxf(-cj / aj, -KCLAMP), KCLAMP) : KCLAMP;
            if (kj < kx || (kj == kx && j < tid)) r++;
        }
        sk[r] = kx;
    }
    __syncthreads();

    // h1[p] exactly at each sorted base knot + probes at sk0-1, sk39+1
    for (int idx = tid; idx < (H0 + 2) * H1; idx += 1024) {
        int k = idx / H1, p = idx % H1;
        float x = (k < H0) ? sk[k] : (k == H0 ? sk[0] - 1.0f : sk[H0 - 1] + 1.0f);
        float acc = sb1[p];
        for (int o = 0; o < H0; o++)
            acc += sW1[o * H1 + p] * fmaxf(sa[o] * x + sc[o], 0.0f);
        sH[k][p] = acc;
    }
    if (tid < H0) list[atomicAdd(&cnt, 1)] = sk[tid];
    if (tid == 0) list[atomicAdd(&cnt, 1)] = XSYNTH;   // synthetic left anchor
    __syncthreads();

    // interior zero-crossings of h1[p]
    for (int idx = tid; idx < (H0 - 1) * H1; idx += 1024) {
        int k = idx / H1, p = idx % H1;
        float y0 = sH[k][p], y1 = sH[k + 1][p];
        if ((y0 > 0.0f) != (y1 > 0.0f)) {
            float xs = sk[k] - y0 * (sk[k + 1] - sk[k]) / (y1 - y0);
            xs = fminf(fmaxf(xs, -KCLAMP), KCLAMP);
            list[atomicAdd(&cnt, 1)] = xs;
        }
    }
    // tail crossings (finite-difference slopes from probes)
    if (tid < H1) {
        int p = tid;
        float y0 = sH[0][p];
        float sl = sH[0][p] - sH[H0][p];
        if (sl != 0.0f && y0 != 0.0f && (y0 / sl) > 0.0f) {
            float xs = fminf(fmaxf(sk[0] - y0 / sl, -KCLAMP), KCLAMP);
            list[atomicAdd(&cnt, 1)] = xs;
        }
        float y1 = sH[H0 - 1][p];
        float sr = sH[H0 + 1][p] - sH[H0 - 1][p];
        if (sr != 0.0f && y1 != 0.0f && (y1 / sr) < 0.0f) {
            float xs = fminf(fmaxf(sk[H0 - 1] - y1 / sr, -KCLAMP), KCLAMP);
            list[atomicAdd(&cnt, 1)] = xs;
        }
    }
    __syncthreads();
    const int n = cnt;   // <= 862

    // stable rank-sort list[0..n) -> sx, pad with +huge
    for (int i = tid; i < n; i += 1024) {
        float v = list[i];
        int r = 0;
        for (int j = 0; j < n; j++) {
            float u = list[j];
            r += (u < v) || (u == v && j < i);
        }
        sx[r] = v;
    }
    for (int i = tid; i < TBL; i += 1024)
        if (i >= n) sx[i] = 3.4e38f;
    __syncthreads();

    // exact full-network evals at every knot + right probe
    for (int idx = tid; idx < n + 1; idx += 1024) {
        float x = (idx == n) ? sx[n - 1] + 1.0f : sx[idx];
        float h1v[H1];
        #pragma unroll
        for (int p = 0; p < H1; p++) h1v[p] = sb1[p];
        for (int o = 0; o < H0; o++) {
            float h0 = fmaxf(sa[o] * x + sc[o], 0.0f);
            #pragma unroll
            for (int p = 0; p < H1; p++) h1v[p] += sW1[o * H1 + p] * h0;
        }
        float yv = sb2v;
        #pragma unroll
        for (int p = 0; p < H1; p++) yv += sW2[p] * fmaxf(h1v[p], 0.0f);
        if (idx == n) syr = yv; else list[idx] = yv;
    }
    __syncthreads();

    // emit table (x, y, slope)
    for (int k = tid; k < TBL; k += 1024) {
        float xk = sx[k];
        float yk = (k < n) ? list[k] : 0.0f;
        float s = 0.0f;
        if (k < n - 1) {
            float dx = sx[k + 1] - xk;
            if (dx > 0.0f) s = (list[k + 1] - yk) / dx;
        } else if (k == n - 1) {
            s = syr - yk;                  // right tail (dx = 1)
        }
        g_x[f][k]  = xk;
        g_ys[f][k] = make_float2(yk, s);
    }
    // bucket LUT: cell c over [-8,8] -> last knot with x <= cell_left
    for (int c = tid; c < NCELL; c += 1024) {
        float cl = -8.0f + (float)c * (16.0f / NCELL);
        int k = 0;
        #pragma unroll
        for (int b = 512; b >= 1; b >>= 1) {
            int t = k + b;
            if (t < TBL && sx[t] <= cl) k = t;
        }
        g_bk[f][c] = (unsigned short)k;
    }
}

// ---------------------------------------------------------------------------
// K1 pre: 128 rows/block, numeric columns -> smem transpose -> g_xT
// (6 independent loads + 6 independent stores per thread = high MLP)
// ---------------------------------------------------------------------------
#define PRER 128

__global__ __launch_bounds__(256)
void gam_pre_kernel(const float* __restrict__ inputs)
{
    __shared__ float s[PRER][NNUM + 1];       // 128 x 49
    const int tid  = threadIdx.x;
    const int row0 = blockIdx.x * PRER;

    const float4* inp4 = (const float4*)(inputs + (size_t)row0 * NFEAT);
    float4 d[6];
    #pragma unroll
    for (int i = 0; i < 6; i++) {             // issue all 6 loads first (MLP=6)
        int v  = i * 256 + tid;
        int r  = v / 12, c4 = v - r * 12;
        d[i] = __ldcs(&inp4[r * 16 + c4]);
    }
    #pragma unroll
    for (int i = 0; i < 6; i++) {
        int v  = i * 256 + tid;
        int r  = v / 12, c4 = v - r * 12;
        s[r][c4 * 4 + 0] = d[i].x; s[r][c4 * 4 + 1] = d[i].y;
        s[r][c4 * 4 + 2] = d[i].z; s[r][c4 * 4 + 3] = d[i].w;
    }
    __syncthreads();

    #pragma unroll
    for (int i = 0; i < 6; i++) {             // 48 feats x 32 row-quads
        int v  = i * 256 + tid;
        int f  = v >> 5, rq = v & 31;
        float4 o = make_float4(s[4 * rq + 0][f], s[4 * rq + 1][f],
                               s[4 * rq + 2][f], s[4 * rq + 3][f]);
        ((float4*)(g_xT + (size_t)f * B_TOTAL + row0))[rq] = o;
    }
}

// ---------------------------------------------------------------------------
// K2 lut: in-place on g_xT; all loads issued before any store (MLP=8)
// ---------------------------------------------------------------------------
__device__ __forceinline__ float lut_eval(float xv, const float* tx,
                                          const float2* tys,
                                          const unsigned short* sb)
{
    int cell = __float2int_rz(fmaf(xv, (float)NCELL / 16.0f, (float)NCELL / 2));
    cell = max(0, min(NCELL - 1, cell));
    int k = sb[cell];
    while (tx[k + 1] <= xv) k++;
    while (k > 0 && tx[k] > xv) k--;          // guard: x below bucket grid
    float2 ys = tys[k];
    return fmaf(xv - tx[k], ys.y, ys.x);
}

#define LROWS 8192
#define LG    (LROWS / 1024)                  // 8 f4 per thread

__global__ __launch_bounds__(256)
void gam_lut_kernel()
{
    __shared__ float          tx[TBL];
    __shared__ float2         tys[TBL];
    __shared__ unsigned short sb[NCELL];
    const int f   = blockIdx.y;
    const int tid = threadIdx.x;

    ((float4*)tx)[tid]        = ((const float4*)g_x[f])[tid];
    ((float4*)tys)[tid]       = ((const float4*)g_ys[f])[tid];
    ((float4*)tys)[256 + tid] = ((const float4*)g_ys[f])[256 + tid];
    ((uint4*)sb)[tid]         = ((const uint4*)g_bk[f])[tid];
    ((uint4*)sb)[256 + tid]   = ((const uint4*)g_bk[f])[256 + tid];
    __syncthreads();

    float4* xc = (float4*)(g_xT + (size_t)f * B_TOTAL) + blockIdx.x * (LROWS / 4);

    float4 xv[LG];
    #pragma unroll
    for (int g = 0; g < LG; g++)              // 8 independent loads in flight
        xv[g] = xc[g * 256 + tid];

    #pragma unroll
    for (int g = 0; g < LG; g++) {
        float4 y4;
        y4.x = lut_eval(xv[g].x, tx, tys, sb);
        y4.y = lut_eval(xv[g].y, tx, tys, sb);
        y4.z = lut_eval(xv[g].z, tx, tys, sb);
        y4.w = lut_eval(xv[g].w, tx, tys, sb);
        xc[g * 256 + tid] = y4;               // in-place overwrite
    }
}

// ---------------------------------------------------------------------------
// K3 post: g_xT (now y) numeric columns + inputs cat columns -> row-major out
// (6+2 independent loads per thread before the sync = high MLP)
// ---------------------------------------------------------------------------
__global__ __launch_bounds__(256)
void gam_post_kernel(const float* __restrict__ inputs,
                     const float* __restrict__ class_bias,
                     float* __restrict__ out)
{
    __shared__ float s[PRER][NFEAT + 1];      // 128 x 65
    __shared__ float scb[NCAT * NCLS];
    const int tid  = threadIdx.x;
    const int row0 = blockIdx.x * PRER;

    if (tid < 128) ((float4*)scb)[tid] = ((const float4*)class_bias)[tid];

    // issue all 8 loads up front
    float4 dn[6], dc[2];
    #pragma unroll
    for (int i = 0; i < 6; i++) {             // numeric: 48 feats x 32 quads
        int v  = i * 256 + tid;
        int f  = v >> 5, rq = v & 31;
        dn[i] = __ldlu(&((const float4*)(g_xT + (size_t)f * B_TOTAL + row0))[rq]);
    }
    const float4* inp4 = (const float4*)(inputs + (size_t)row0 * NFEAT);
    #pragma unroll
    for (int i = 0; i < 2; i++) {             // cat: 128 rows x 4 f4
        int v  = i * 256 + tid;
        int r  = v >> 2, cc = v & 3;
        dc[i] = __ldcs(&inp4[r * 16 + 12 + cc]);
    }

    #pragma unroll
    for (int i = 0; i < 6; i++) {
        int v  = i * 256 + tid;
        int f  = v >> 5, rq = v & 31;
        s[4 * rq + 0][f] = dn[i].x; s[4 * rq + 1][f] = dn[i].y;
        s[4 * rq + 2][f] = dn[i].z; s[4 * rq + 3][f] = dn[i].w;
    }
    __syncthreads();                          // scb ready before cat scatter
    #pragma unroll
    for (int i = 0; i < 2; i++) {
        int v  = i * 256 + tid;
        int r  = v >> 2, cc = v & 3;
        s[r][48 + cc * 4 + 0] = scb[(cc * 4 + 0) * NCLS + (int)dc[i].x];
        s[r][48 + cc * 4 + 1] = scb[(cc * 4 + 1) * NCLS + (int)dc[i].y];
        s[r][48 + cc * 4 + 2] = scb[(cc * 4 + 2) * NCLS + (int)dc[i].z];
        s[r][48 + cc * 4 + 3] = scb[(cc * 4 + 3) * NCLS + (int)dc[i].w];
    }
    __syncthreads();

    float4* out4 = (float4*)(out + (size_t)row0 * NFEAT);
    #pragma unroll
    for (int i = 0; i < 8; i++) {             // 128 rows x 16 f4 — streaming stores
        int v  = i * 256 + tid;
        int r  = v >> 4, c4 = v & 15;
        __stcs(&out4[v], make_float4(s[r][4 * c4 + 0], s[r][4 * c4 + 1],
                                     s[r][4 * c4 + 2], s[r][4 * c4 + 3]));
    }
}

extern "C" void kernel_launch(void* const* d_in, const int* in_sizes, int n_in,
                              void* d_out, int out_size)
{
    const float* inputs     = (const float*)d_in[0];
    const float* W0         = (const float*)d_in[1];
    const float* b0         = (const float*)d_in[2];
    const float* W1         = (const float*)d_in[3];
    const float* b1         = (const float*)d_in[4];
    const float* W2         = (const float*)d_in[5];
    const float* b2         = (const float*)d_in[6];
    const float* class_bias = (const float*)d_in[7];
    float* out = (float*)d_out;

    gam_setup_kernel<<<NNUM, 1024>>>(W0, b0, W1, b1, W2, b2);
    gam_pre_kernel<<<B_TOTAL / PRER, 256>>>(inputs);
    dim3 g2(B_TOTAL / LROWS, NNUM);           // 16 x 48
    gam_lut_kernel<<<g2, 256>>>();
    gam_post_kernel<<<B_TOTAL / PRER, 256>>>(inputs, class_bias, out);
}

// round 11
// speedup vs baseline: 1.0493x; 1.0493x over previous
#include <cuda_runtime.h>

#define B_TOTAL 131072
#define NFEAT   64
#define NNUM    48
#define NCAT    16
#define NCLS    32
#define H0      40
#define H1      20
#define TBL     1024
#define NCELL   4096
#define KCLAMP  1.0e4f
#define XSYNTH  -16.0f

#define PRER    64
#define NPRE    (B_TOTAL / PRER)      // 2048 pre blocks

// device-global scratch (allocation-free)
__device__ float          g_x[NNUM][TBL];     // knot x, padded +huge
__device__ float2         g_ys[NNUM][TBL];    // (y, slope-to-next)
__device__ unsigned short g_bk[NNUM][NCELL];  // bucket -> knot index
__device__ float          g_xT[NNUM * B_TOTAL];  // col-major x, overwritten with y in-place

// ---------------------------------------------------------------------------
// Setup body (256 threads): exact PWL table for feature f.
// Net is exactly PWL in scalar x: knots = layer0 zeros U h1 zero-crossings.
// Shared carved from the caller's union buffer.
// ---------------------------------------------------------------------------
__device__ void setup_body(int f, int tid, float* sh,
                           const float* __restrict__ W0, const float* __restrict__ b0,
                           const float* __restrict__ W1, const float* __restrict__ b1,
                           const float* __restrict__ W2, const float* __restrict__ b2)
{
    float* sW1  = sh;                 // 800
    float* list = sh + 800;           // 1024
    float* sx   = sh + 1824;          // 1024
    float* sHf  = sh + 2848;          // 42*20 = 840
    float* sa   = sh + 3688;          // 40
    float* sc   = sh + 3728;          // 40
    float* sk   = sh + 3768;          // 40
    float* sb1  = sh + 3808;          // 20
    float* sW2  = sh + 3828;          // 20
    float* syr  = sh + 3848;          // 1
    float* sb2v = sh + 3849;          // 1
    int*   cnt  = (int*)(sh + 3850);  // 1
    #define SH(k, p) sHf[(k) * H1 + (p)]

    if (tid == 0) *cnt = 0;
    if (tid < H0) { sa[tid] = W0[f * H0 + tid]; sc[tid] = b0[f * H0 + tid]; }
    for (int i = tid; i < H0 * H1; i += 256) sW1[i] = W1[f * H0 * H1 + i];
    if (tid < H1) { sb1[tid] = b1[f * H1 + tid]; sW2[tid] = W2[f * H1 + tid]; }
    if (tid == 0) *sb2v = b2[f];
    __syncthreads();

    // layer0 knots (clamped), stable rank-sort into sk
    if (tid < H0) {
        float a = sa[tid], c = sc[tid];
        float kx = (a != 0.0f) ? fminf(fmaxf(-c / a, -KCLAMP), KCLAMP) : KCLAMP;
        int r = 0;
        for (int j = 0; j < H0; j++) {
            float aj = sa[j], cj = sc[j];
            float kj = (aj != 0.0f) ? fminf(fmaxf(-cj / aj, -KCLAMP), KCLAMP) : KCLAMP;
            if (kj < kx || (kj == kx && j < tid)) r++;
        }
        sk[r] = kx;
    }
    __syncthreads();

    // h1[p] exactly at each sorted base knot + probes at sk0-1, sk39+1
    for (int idx = tid; idx < (H0 + 2) * H1; idx += 256) {
        int k = idx / H1, p = idx % H1;
        float x = (k < H0) ? sk[k] : (k == H0 ? sk[0] - 1.0f : sk[H0 - 1] + 1.0f);
        float acc = sb1[p];
        for (int o = 0; o < H0; o++)
            acc += sW1[o * H1 + p] * fmaxf(sa[o] * x + sc[o], 0.0f);
        SH(k, p) = acc;
    }
    if (tid < H0) list[atomicAdd(cnt, 1)] = sk[tid];
    if (tid == 0) list[atomicAdd(cnt, 1)] = XSYNTH;   // synthetic left anchor
    __syncthreads();

    // interior zero-crossings of h1[p]
    for (int idx = tid; idx < (H0 - 1) * H1; idx += 256) {
        int k = idx / H1, p = idx % H1;
        float y0 = SH(k, p), y1 = SH(k + 1, p);
        if ((y0 > 0.0f) != (y1 > 0.0f)) {
            float xs = sk[k] - y0 * (sk[k + 1] - sk[k]) / (y1 - y0);
            xs = fminf(fmaxf(xs, -KCLAMP), KCLAMP);
            list[atomicAdd(cnt, 1)] = xs;
        }
    }
    // tail crossings (finite-difference slopes from probes)
    if (tid < H1) {
        int p = tid;
        float y0 = SH(0, p);
        float sl = SH(0, p) - SH(H0, p);
        if (sl != 0.0f && y0 != 0.0f && (y0 / sl) > 0.0f) {
            float xs = fminf(fmaxf(sk[0] - y0 / sl, -KCLAMP), KCLAMP);
            list[atomicAdd(cnt, 1)] = xs;
        }
        float y1 = SH(H0 - 1, p);
        float sr = SH(H0 + 1, p) - SH(H0 - 1, p);
        if (sr != 0.0f && y1 != 0.0f && (y1 / sr) < 0.0f) {
            float xs = fminf(fmaxf(sk[H0 - 1] - y1 / sr, -KCLAMP), KCLAMP);
            list[atomicAdd(cnt, 1)] = xs;
        }
    }
    __syncthreads();
    const int n = *cnt;   // <= 862

    // stable rank-sort list[0..n) -> sx, pad with +huge
    for (int i = tid; i < n; i += 256) {
        float v = list[i];
        int r = 0;
        for (int j = 0; j < n; j++) {
            float u = list[j];
            r += (u < v) || (u == v && j < i);
        }
        sx[r] = v;
    }
    for (int i = tid; i < TBL; i += 256)
        if (i >= n) sx[i] = 3.4e38f;
    __syncthreads();

    // exact full-network evals at every knot + right probe
    for (int idx = tid; idx < n + 1; idx += 256) {
        float x = (idx == n) ? sx[n - 1] + 1.0f : sx[idx];
        float h1v[H1];
        #pragma unroll
        for (int p = 0; p < H1; p++) h1v[p] = sb1[p];
        for (int o = 0; o < H0; o++) {
            float h0 = fmaxf(sa[o] * x + sc[o], 0.0f);
            #pragma unroll
            for (int p = 0; p < H1; p++) h1v[p] += sW1[o * H1 + p] * h0;
        }
        float yv = *sb2v;
        #pragma unroll
        for (int p = 0; p < H1; p++) yv += sW2[p] * fmaxf(h1v[p], 0.0f);
        if (idx == n) *syr = yv; else list[idx] = yv;
    }
    __syncthreads();

    // emit table (x, y, slope)
    for (int k = tid; k < TBL; k += 256) {
        float xk = sx[k];
        float yk = (k < n) ? list[k] : 0.0f;
        float s = 0.0f;
        if (k < n - 1) {
            float dx = sx[k + 1] - xk;
            if (dx > 0.0f) s = (list[k + 1] - yk) / dx;
        } else if (k == n - 1) {
            s = *syr - yk;                 // right tail (dx = 1)
        }
        g_x[f][k]  = xk;
        g_ys[f][k] = make_float2(yk, s);
    }
    // bucket LUT: cell c over [-8,8] -> last knot with x <= cell_left
    for (int c = tid; c < NCELL; c += 256) {
        float cl = -8.0f + (float)c * (16.0f / NCELL);
        int k = 0;
        #pragma unroll
        for (int b = 512; b >= 1; b >>= 1) {
            int t = k + b;
            if (t < TBL && sx[t] <= cl) k = t;
        }
        g_bk[f][c] = (unsigned short)k;
    }
    #undef SH
}

// ---------------------------------------------------------------------------
// Pre body: 64 rows -> smem transpose -> g_xT (numeric only)
// ---------------------------------------------------------------------------
__device__ void pre_body(int blk, int tid, float* sh,
                         const float* __restrict__ inputs)
{
    float (*s)[NNUM + 1] = (float (*)[NNUM + 1])sh;   // 64 x 49
    const int row0 = blk * PRER;

    const float4* inp4 = (const float4*)(inputs + (size_t)row0 * NFEAT);
    float4 d[3];
    #pragma unroll
    for (int i = 0; i < 3; i++) {             // 64 rows x 12 numeric f4, MLP=3
        int v  = i * 256 + tid;
        int r  = v / 12, c4 = v - r * 12;
        d[i] = __ldcs(&inp4[r * 16 + c4]);
    }
    #pragma unroll
    for (int i = 0; i < 3; i++) {
        int v  = i * 256 + tid;
        int r  = v / 12, c4 = v - r * 12;
        s[r][c4 * 4 + 0] = d[i].x; s[r][c4 * 4 + 1] = d[i].y;
        s[r][c4 * 4 + 2] = d[i].z; s[r][c4 * 4 + 3] = d[i].w;
    }
    __syncthreads();

    #pragma unroll
    for (int i = 0; i < 3; i++) {             // 48 feats x 16 row-quads
        int v  = i * 256 + tid;
        int f  = v >> 4, rq = v & 15;
        float4 o = make_float4(s[4 * rq + 0][f], s[4 * rq + 1][f],
                               s[4 * rq + 2][f], s[4 * rq + 3][f]);
        ((float4*)(g_xT + (size_t)f * B_TOTAL + row0))[rq] = o;
    }
}

// Fused: blocks [0,NPRE) transpose; blocks [NPRE,NPRE+48) build tables.
__global__ __launch_bounds__(256)
void gam_pre_setup_kernel(const float* __restrict__ inputs,
                          const float* __restrict__ W0, const float* __restrict__ b0,
                          const float* __restrict__ W1, const float* __restrict__ b1,
                          const float* __restrict__ W2, const float* __restrict__ b2)
{
    __shared__ __align__(16) float sh[3904];   // union: setup 3851f / pre 3136f
    if (blockIdx.x < NPRE)
        pre_body(blockIdx.x, threadIdx.x, sh, inputs);
    else
        setup_body(blockIdx.x - NPRE, threadIdx.x, sh, W0, b0, W1, b1, W2, b2);
}

// ---------------------------------------------------------------------------
// K2 lut: in-place on g_xT; all loads issued before any store (MLP=8)
// ---------------------------------------------------------------------------
__device__ __forceinline__ float lut_eval(float xv, const float* tx,
                                          const float2* tys,
                                          const unsigned short* sb)
{
    int cell = __float2int_rz(fmaf(xv, (float)NCELL / 16.0f, (float)NCELL / 2));
    cell = max(0, min(NCELL - 1, cell));
    int k = sb[cell];
    while (tx[k + 1] <= xv) k++;
    while (k > 0 && tx[k] > xv) k--;          // guard: x below bucket grid
    float2 ys = tys[k];
    return fmaf(xv - tx[k], ys.y, ys.x);
}

#define LROWS 8192
#define LG    (LROWS / 1024)                  // 8 f4 per thread

__global__ __launch_bounds__(256)
void gam_lut_kernel()
{
    __shared__ float          tx[TBL];
    __shared__ float2         tys[TBL];
    __shared__ unsigned short sb[NCELL];
    const int f   = blockIdx.y;
    const int tid = threadIdx.x;

    ((float4*)tx)[tid]        = ((const float4*)g_x[f])[tid];
    ((float4*)tys)[tid]       = ((const float4*)g_ys[f])[tid];
    ((float4*)tys)[256 + tid] = ((const float4*)g_ys[f])[256 + tid];
    ((uint4*)sb)[tid]         = ((const uint4*)g_bk[f])[tid];
    ((uint4*)sb)[256 + tid]   = ((const uint4*)g_bk[f])[256 + tid];
    __syncthreads();

    float4* xc = (float4*)(g_xT + (size_t)f * B_TOTAL) + blockIdx.x * (LROWS / 4);

    float4 xv[LG];
    #pragma unroll
    for (int g = 0; g < LG; g++)              // 8 independent loads in flight
        xv[g] = xc[g * 256 + tid];

    #pragma unroll
    for (int g = 0; g < LG; g++) {
        float4 y4;
        y4.x = lut_eval(xv[g].x, tx, tys, sb);
        y4.y = lut_eval(xv[g].y, tx, tys, sb);
        y4.z = lut_eval(xv[g].z, tx, tys, sb);
        y4.w = lut_eval(xv[g].w, tx, tys, sb);
        xc[g * 256 + tid] = y4;               // in-place overwrite
    }
}

// ---------------------------------------------------------------------------
// K3 post: g_xT (now y) numeric columns + inputs cat columns -> row-major out
// (round-8 configuration: 64 rows/block, 82% occupancy)
// ---------------------------------------------------------------------------
__global__ __launch_bounds__(256)
void gam_post_kernel(const float* __restrict__ inputs,
                     const float* __restrict__ class_bias,
                     float* __restrict__ out)
{
    __shared__ float s[PRER][NFEAT + 1];      // 64 x 65
    __shared__ float scb[NCAT * NCLS];
    const int tid  = threadIdx.x;
    const int row0 = blockIdx.x * PRER;

    if (tid < 128) ((float4*)scb)[tid] = ((const float4*)class_bias)[tid];

    #pragma unroll
    for (int i = 0; i < 3; i++) {             // numeric: 48 feats x 16 quads
        int v  = i * 256 + tid;
        int f  = v >> 4, rq = v & 15;
        float4 d = __ldlu(&((const float4*)(g_xT + (size_t)f * B_TOTAL + row0))[rq]);
        s[4 * rq + 0][f] = d.x; s[4 * rq + 1][f] = d.y;
        s[4 * rq + 2][f] = d.z; s[4 * rq + 3][f] = d.w;
    }
    {                                          // cat: 64 rows x 4 f4 (1/thread)
        int r = tid >> 2, cc = tid & 3;
        const float4* inp4 = (const float4*)(inputs + (size_t)row0 * NFEAT);
        float4 d = __ldcs(&inp4[r * 16 + 12 + cc]);
        __syncthreads();                       // scb ready (covers numeric too)
        s[r][48 + cc * 4 + 0] = scb[(cc * 4 + 0) * NCLS + (int)d.x];
        s[r][48 + cc * 4 + 1] = scb[(cc * 4 + 1) * NCLS + (int)d.y];
        s[r][48 + cc * 4 + 2] = scb[(cc * 4 + 2) * NCLS + (int)d.z];
        s[r][48 + cc * 4 + 3] = scb[(cc * 4 + 3) * NCLS + (int)d.w];
    }
    __syncthreads();

    float4* out4 = (float4*)(out + (size_t)row0 * NFEAT);
    #pragma unroll
    for (int i = 0; i < 4; i++) {             // 64 rows x 16 f4 — streaming stores
        int v  = i * 256 + tid;
        int r  = v >> 4, c4 = v & 15;
        __stcs(&out4[v], make_float4(s[r][4 * c4 + 0], s[r][4 * c4 + 1],
                                     s[r][4 * c4 + 2], s[r][4 * c4 + 3]));
    }
}

extern "C" void kernel_launch(void* const* d_in, const int* in_sizes, int n_in,
                              void* d_out, int out_size)
{
    const float* inputs     = (const float*)d_in[0];
    const float* W0         = (const float*)d_in[1];
    const float* b0         = (const float*)d_in[2];
    const float* W1         = (const float*)d_in[3];
    const float* b1         = (const float*)d_in[4];
    const float* W2         = (const float*)d_in[5];
    const float* b2         = (const float*)d_in[6];
    const float* class_bias = (const float*)d_in[7];
    float* out = (float*)d_out;

    gam_pre_setup_kernel<<<NPRE + NNUM, 256>>>(inputs, W0, b0, W1, b1, W2, b2);
    dim3 g2(B_TOTAL / LROWS, NNUM);           // 16 x 48
    gam_lut_kernel<<<g2, 256>>>();
    gam_post_kernel<<<B_TOTAL / PRER, 256>>>(inputs, class_bias, out);
}